// round 1
// baseline (speedup 1.0000x reference)
#include <cuda_runtime.h>

#define N_NODES 100000
#define N_EDGES 1600000
#define D       64
#define DH      128
#define KIN     192      // D_EDGE + 2*D_NODE

#define TILE_E  64
#define APAD    72
#define EK_THREADS 256

// ---------------- scratch (static device global: no allocs allowed) ----------
__device__ float g_agg[(size_t)N_NODES * D];

// ---------------- shared memory layout for edge kernel (float offsets) -------
#define OFF_W1   0                         // 192*128 = 24576
#define OFF_W2   (OFF_W1 + KIN * DH)       //  8192
#define OFF_WE   (OFF_W2 + DH * D)         //  8192
#define OFF_B1   (OFF_WE + DH * D)         //   128
#define OFF_B2   (OFF_B1 + DH)             //    64
#define OFF_BE   (OFF_B2 + D)              //    64
#define OFF_A    (OFF_BE + D)              // 192*72 = 13824 (K-major tile)
#define OFF_RIDX (OFF_A + KIN * APAD)      //    64 (ints)
#define SMEM_EDGE_FLOATS (OFF_RIDX + 64)
#define SMEM_EDGE_BYTES  (SMEM_EDGE_FLOATS * 4)

// ---------------- zero the aggregation buffer --------------------------------
__global__ void zero_agg_kernel() {
    size_t i = (size_t)blockIdx.x * blockDim.x + threadIdx.x;
    size_t n4 = (size_t)N_NODES * D / 4;
    if (i < n4) ((float4*)g_agg)[i] = make_float4(0.f, 0.f, 0.f, 0.f);
}

// ---------------- fused edge kernel ------------------------------------------
// per 64-edge tile:
//   gather  [e | h[s] | h[r]] -> A rows 0..191   (K-major)
//   GEMM1: hid = relu(A(0:192) @ W1 + b1)        -> overlay A rows 64..191
//   GEMM2: m   = hid @ W2 + b2                   -> overlay A rows 64..127
//   scatter: atomicAdd(g_agg[r], m)              (issued before GEMM3)
//   GEMM3: e_new = relu(A(0:128) @ We + be)      -> gmem
__global__ void __launch_bounds__(EK_THREADS, 1)
edge_kernel(const float* __restrict__ h, const float* __restrict__ e,
            const int* __restrict__ senders, const int* __restrict__ receivers,
            const float* __restrict__ W1, const float* __restrict__ b1,
            const float* __restrict__ W2, const float* __restrict__ b2,
            const float* __restrict__ We, const float* __restrict__ be,
            float* __restrict__ out_e)
{
    extern __shared__ float sm[];
    const int tid = threadIdx.x;

    // stage weights (L2 -> smem) once per block
    for (int i = tid; i < KIN * DH / 4; i += EK_THREADS)
        ((float4*)(sm + OFF_W1))[i] = ((const float4*)W1)[i];
    for (int i = tid; i < DH * D / 4; i += EK_THREADS)
        ((float4*)(sm + OFF_W2))[i] = ((const float4*)W2)[i];
    for (int i = tid; i < DH * D / 4; i += EK_THREADS)
        ((float4*)(sm + OFF_WE))[i] = ((const float4*)We)[i];
    if (tid < DH) sm[OFF_B1 + tid] = b1[tid];
    if (tid < D)  sm[OFF_B2 + tid] = b2[tid];
    else if (tid < 2 * D) sm[OFF_BE + tid - D] = be[tid - D];
    __syncthreads();

    // thread maps
    const int el   = tid >> 2;   // gather: edge 0..63
    const int part = tid & 3;    // gather: 16-float chunk
    const int eg   = tid >> 5;   // GEMM1: 8 edges
    const int cg   = tid & 31;   // GEMM1: 4 cols
    const int eg2  = tid >> 4;   // GEMM2/3: 4 edges
    const int cg2  = tid & 15;   // GEMM2/3: 4 cols
    const int sj   = tid & 63;   // scatter: feature col
    const int sgrp = tid >> 6;   // scatter: edge group (16 edges)

    int* ridx = (int*)(sm + OFF_RIDX);

    const int n_tiles = N_EDGES / TILE_E;
    for (int tile = blockIdx.x; tile < n_tiles; tile += gridDim.x) {
        const int base = tile * TILE_E;

        // ---- gather (transposed K-major writes) ----
        {
            const int s = senders[base + el];
            const int r = receivers[base + el];
            if (part == 0) ridx[el] = r;
            const float4* ep = (const float4*)(e + (size_t)(base + el) * D) + part * 4;
            const float4* hs = (const float4*)(h + (size_t)s * D) + part * 4;
            const float4* hr = (const float4*)(h + (size_t)r * D) + part * 4;
            #pragma unroll
            for (int q = 0; q < 4; q++) {
                float4 v = ep[q];
                int k0 = part * 16 + q * 4;
                sm[OFF_A + (k0 + 0) * APAD + el] = v.x;
                sm[OFF_A + (k0 + 1) * APAD + el] = v.y;
                sm[OFF_A + (k0 + 2) * APAD + el] = v.z;
                sm[OFF_A + (k0 + 3) * APAD + el] = v.w;
            }
            #pragma unroll
            for (int q = 0; q < 4; q++) {
                float4 v = hs[q];
                int k0 = 64 + part * 16 + q * 4;
                sm[OFF_A + (k0 + 0) * APAD + el] = v.x;
                sm[OFF_A + (k0 + 1) * APAD + el] = v.y;
                sm[OFF_A + (k0 + 2) * APAD + el] = v.z;
                sm[OFF_A + (k0 + 3) * APAD + el] = v.w;
            }
            #pragma unroll
            for (int q = 0; q < 4; q++) {
                float4 v = hr[q];
                int k0 = 128 + part * 16 + q * 4;
                sm[OFF_A + (k0 + 0) * APAD + el] = v.x;
                sm[OFF_A + (k0 + 1) * APAD + el] = v.y;
                sm[OFF_A + (k0 + 2) * APAD + el] = v.z;
                sm[OFF_A + (k0 + 3) * APAD + el] = v.w;
            }
        }
        __syncthreads();

        // ---- GEMM1: [64,192] @ [192,128], micro 8e x 4c ----
        {
            float acc[8][4];
            #pragma unroll
            for (int i = 0; i < 8; i++)
                #pragma unroll
                for (int j = 0; j < 4; j++) acc[i][j] = 0.f;

            const float* Ab = sm + OFF_A + eg * 8;
            const float* Wb = sm + OFF_W1 + cg * 4;
            #pragma unroll 4
            for (int k = 0; k < KIN; k++) {
                float4 a0 = *(const float4*)(Ab + k * APAD);
                float4 a1 = *(const float4*)(Ab + k * APAD + 4);
                float4 w  = *(const float4*)(Wb + k * DH);
                float a[8] = {a0.x, a0.y, a0.z, a0.w, a1.x, a1.y, a1.z, a1.w};
                float wv[4] = {w.x, w.y, w.z, w.w};
                #pragma unroll
                for (int i = 0; i < 8; i++)
                    #pragma unroll
                    for (int j = 0; j < 4; j++)
                        acc[i][j] = fmaf(a[i], wv[j], acc[i][j]);
            }
            __syncthreads();
            float bb[4];
            #pragma unroll
            for (int j = 0; j < 4; j++) bb[j] = sm[OFF_B1 + cg * 4 + j];
            #pragma unroll
            for (int i = 0; i < 8; i++) {
                int eli = eg * 8 + i;
                #pragma unroll
                for (int j = 0; j < 4; j++)
                    sm[OFF_A + (64 + cg * 4 + j) * APAD + eli] =
                        fmaxf(acc[i][j] + bb[j], 0.f);
            }
        }
        __syncthreads();

        // ---- GEMM2: [64,128] @ [128,64], micro 4e x 4c ----
        {
            float acc[4][4];
            #pragma unroll
            for (int i = 0; i < 4; i++)
                #pragma unroll
                for (int j = 0; j < 4; j++) acc[i][j] = 0.f;

            const float* Ab = sm + OFF_A + 64 * APAD + eg2 * 4;
            const float* Wb = sm + OFF_W2 + cg2 * 4;
            #pragma unroll 4
            for (int k = 0; k < DH; k++) {
                float4 a = *(const float4*)(Ab + k * APAD);
                float4 w = *(const float4*)(Wb + k * D);
                float av[4] = {a.x, a.y, a.z, a.w};
                float wv[4] = {w.x, w.y, w.z, w.w};
                #pragma unroll
                for (int i = 0; i < 4; i++)
                    #pragma unroll
                    for (int j = 0; j < 4; j++)
                        acc[i][j] = fmaf(av[i], wv[j], acc[i][j]);
            }
            __syncthreads();
            float bb[4];
            #pragma unroll
            for (int j = 0; j < 4; j++) bb[j] = sm[OFF_B2 + cg2 * 4 + j];
            #pragma unroll
            for (int i = 0; i < 4; i++) {
                int eli = eg2 * 4 + i;
                #pragma unroll
                for (int j = 0; j < 4; j++)
                    sm[OFF_A + (64 + cg2 * 4 + j) * APAD + eli] = acc[i][j] + bb[j];
            }
        }
        __syncthreads();

        // ---- scatter m into g_agg (fire-and-forget, overlaps GEMM3) ----
        #pragma unroll 4
        for (int ii = 0; ii < 16; ii++) {
            int els = sgrp * 16 + ii;
            int r = ridx[els];
            atomicAdd(&g_agg[(size_t)r * D + sj], sm[OFF_A + (64 + sj) * APAD + els]);
        }

        // ---- GEMM3: [64,128] @ [128,64] -> e_new ----
        {
            float acc[4][4];
            #pragma unroll
            for (int i = 0; i < 4; i++)
                #pragma unroll
                for (int j = 0; j < 4; j++) acc[i][j] = 0.f;

            const float* Ab = sm + OFF_A + eg2 * 4;
            const float* Wb = sm + OFF_WE + cg2 * 4;
            #pragma unroll 4
            for (int k = 0; k < DH; k++) {
                float4 a = *(const float4*)(Ab + k * APAD);
                float4 w = *(const float4*)(Wb + k * D);
                float av[4] = {a.x, a.y, a.z, a.w};
                float wv[4] = {w.x, w.y, w.z, w.w};
                #pragma unroll
                for (int i = 0; i < 4; i++)
                    #pragma unroll
                    for (int j = 0; j < 4; j++)
                        acc[i][j] = fmaf(av[i], wv[j], acc[i][j]);
            }
            float bb[4];
            #pragma unroll
            for (int j = 0; j < 4; j++) bb[j] = sm[OFF_BE + cg2 * 4 + j];
            #pragma unroll
            for (int i = 0; i < 4; i++) {
                float4 v;
                v.x = fmaxf(acc[i][0] + bb[0], 0.f);
                v.y = fmaxf(acc[i][1] + bb[1], 0.f);
                v.z = fmaxf(acc[i][2] + bb[2], 0.f);
                v.w = fmaxf(acc[i][3] + bb[3], 0.f);
                *(float4*)(out_e + (size_t)(base + eg2 * 4 + i) * D + cg2 * 4) = v;
            }
        }
        __syncthreads();   // protect A / ridx before next tile's gather
    }
}

// ---------------- node kernel: h_new = relu([h | agg] @ W_node + b) ----------
#define NT    32
#define NPAD  36
#define NOFF_W 0
#define NOFF_B (NOFF_W + DH * D)      // 8192
#define NOFF_X (NOFF_B + D)           // 8256
#define SMEM_NODE_FLOATS (NOFF_X + DH * NPAD)
#define SMEM_NODE_BYTES  (SMEM_NODE_FLOATS * 4)

__global__ void __launch_bounds__(128)
node_kernel(const float* __restrict__ h,
            const float* __restrict__ Wn, const float* __restrict__ bn,
            float* __restrict__ out_h)
{
    extern __shared__ float sm[];
    const int tid = threadIdx.x;

    for (int i = tid; i < DH * D / 4; i += 128)
        ((float4*)(sm + NOFF_W))[i] = ((const float4*)Wn)[i];
    if (tid < D) sm[NOFF_B + tid] = bn[tid];
    __syncthreads();

    const int nl   = tid >> 2;   // 0..31
    const int part = tid & 3;
    const int ng   = tid >> 4;   // 0..7 (4 nodes)
    const int cgc  = tid & 15;   // 4 cols

    const int n_tiles = N_NODES / NT;
    for (int tile = blockIdx.x; tile < n_tiles; tile += gridDim.x) {
        const int base = tile * NT;
        // gather (contiguous rows, transposed K-major store)
        {
            const float4* hp = (const float4*)(h + (size_t)(base + nl) * D) + part * 4;
            const float4* ap = (const float4*)(g_agg + (size_t)(base + nl) * D) + part * 4;
            #pragma unroll
            for (int q = 0; q < 4; q++) {
                float4 v = hp[q];
                int k0 = part * 16 + q * 4;
                sm[NOFF_X + (k0 + 0) * NPAD + nl] = v.x;
                sm[NOFF_X + (k0 + 1) * NPAD + nl] = v.y;
                sm[NOFF_X + (k0 + 2) * NPAD + nl] = v.z;
                sm[NOFF_X + (k0 + 3) * NPAD + nl] = v.w;
            }
            #pragma unroll
            for (int q = 0; q < 4; q++) {
                float4 v = ap[q];
                int k0 = 64 + part * 16 + q * 4;
                sm[NOFF_X + (k0 + 0) * NPAD + nl] = v.x;
                sm[NOFF_X + (k0 + 1) * NPAD + nl] = v.y;
                sm[NOFF_X + (k0 + 2) * NPAD + nl] = v.z;
                sm[NOFF_X + (k0 + 3) * NPAD + nl] = v.w;
            }
        }
        __syncthreads();

        float acc[4][4];
        #pragma unroll
        for (int i = 0; i < 4; i++)
            #pragma unroll
            for (int j = 0; j < 4; j++) acc[i][j] = 0.f;

        const float* Xb = sm + NOFF_X + ng * 4;
        const float* Wb = sm + NOFF_W + cgc * 4;
        #pragma unroll 4
        for (int k = 0; k < DH; k++) {
            float4 a = *(const float4*)(Xb + k * NPAD);
            float4 w = *(const float4*)(Wb + k * D);
            float av[4] = {a.x, a.y, a.z, a.w};
            float wv[4] = {w.x, w.y, w.z, w.w};
            #pragma unroll
            for (int i = 0; i < 4; i++)
                #pragma unroll
                for (int j = 0; j < 4; j++)
                    acc[i][j] = fmaf(av[i], wv[j], acc[i][j]);
        }
        float bb[4];
        #pragma unroll
        for (int j = 0; j < 4; j++) bb[j] = sm[NOFF_B + cgc * 4 + j];
        #pragma unroll
        for (int i = 0; i < 4; i++) {
            float4 v;
            v.x = fmaxf(acc[i][0] + bb[0], 0.f);
            v.y = fmaxf(acc[i][1] + bb[1], 0.f);
            v.z = fmaxf(acc[i][2] + bb[2], 0.f);
            v.w = fmaxf(acc[i][3] + bb[3], 0.f);
            *(float4*)(out_h + (size_t)(base + ng * 4 + i) * D + cgc * 4) = v;
        }
        __syncthreads();
    }
}

// ---------------- launch -----------------------------------------------------
extern "C" void kernel_launch(void* const* d_in, const int* in_sizes, int n_in,
                              void* d_out, int out_size)
{
    const float* h        = (const float*)d_in[0];
    const float* e        = (const float*)d_in[1];
    const int*   senders  = (const int*)d_in[2];
    const int*   receivers= (const int*)d_in[3];
    const float* W1       = (const float*)d_in[4];
    const float* b1       = (const float*)d_in[5];
    const float* W2       = (const float*)d_in[6];
    const float* b2       = (const float*)d_in[7];
    const float* Wn       = (const float*)d_in[8];
    const float* bn       = (const float*)d_in[9];
    const float* We       = (const float*)d_in[10];
    const float* be       = (const float*)d_in[11];

    float* out_h = (float*)d_out;
    float* out_e = out_h + (size_t)N_NODES * D;

    cudaFuncSetAttribute(edge_kernel, cudaFuncAttributeMaxDynamicSharedMemorySize,
                         SMEM_EDGE_BYTES);
    cudaFuncSetAttribute(node_kernel, cudaFuncAttributeMaxDynamicSharedMemorySize,
                         SMEM_NODE_BYTES);

    zero_agg_kernel<<<(N_NODES * D / 4 + 255) / 256, 256>>>();
    edge_kernel<<<2960, EK_THREADS, SMEM_EDGE_BYTES>>>(
        h, e, senders, receivers, W1, b1, W2, b2, We, be, out_e);
    node_kernel<<<1480, 128, SMEM_NODE_BYTES>>>(h, Wn, bn, out_h);
}

// round 2
// speedup vs baseline: 1.0924x; 1.0924x over previous
#include <cuda_runtime.h>

#define N_NODES 100000
#define N_EDGES 1600000
#define D       64
#define DH      128
#define KIN     192      // D_EDGE + 2*D_NODE

#define TILE_E  64
#define APAD    72
#define EK_THREADS 256

typedef unsigned long long u64;

// ---------------- f32x2 packed helpers (PTX-only on sm_103a) -----------------
__device__ __forceinline__ void fma2(u64& d, u64 a, u64 b, u64 c) {
    asm("fma.rn.f32x2 %0, %1, %2, %3;" : "=l"(d) : "l"(a), "l"(b), "l"(c));
}
__device__ __forceinline__ u64 dupf(float x) {
    u64 d; asm("mov.b64 %0, {%1, %1};" : "=l"(d) : "f"(x)); return d;
}
__device__ __forceinline__ void unpack2(u64 v, float& lo, float& hi) {
    unsigned a, b;
    asm("mov.b64 {%0, %1}, %2;" : "=r"(a), "=r"(b) : "l"(v));
    lo = __uint_as_float(a); hi = __uint_as_float(b);
}

// ---------------- scratch (static device global: no allocs allowed) ----------
__device__ float g_agg[(size_t)N_NODES * D];

// ---------------- shared memory layout for edge kernel (float offsets) -------
#define OFF_W1   0                         // 192*128 = 24576
#define OFF_W2   (OFF_W1 + KIN * DH)       //  8192
#define OFF_WE   (OFF_W2 + DH * D)         //  8192
#define OFF_B1   (OFF_WE + DH * D)         //   128
#define OFF_B2   (OFF_B1 + DH)             //    64
#define OFF_BE   (OFF_B2 + D)              //    64
#define OFF_A    (OFF_BE + D)              // 192*72 = 13824 (K-major tile)
#define OFF_RIDX (OFF_A + KIN * APAD)      //    64 (ints)
#define SMEM_EDGE_FLOATS (OFF_RIDX + 64)
#define SMEM_EDGE_BYTES  (SMEM_EDGE_FLOATS * 4)

// ---------------- zero the aggregation buffer --------------------------------
__global__ void zero_agg_kernel() {
    size_t i = (size_t)blockIdx.x * blockDim.x + threadIdx.x;
    size_t n4 = (size_t)N_NODES * D / 4;
    if (i < n4) ((float4*)g_agg)[i] = make_float4(0.f, 0.f, 0.f, 0.f);
}

// ---------------- fused edge kernel ------------------------------------------
// per 64-edge tile:
//   gather  [e | h[s] | h[r]] -> A rows 0..191   (K-major)
//   GEMM1: hid = relu(A(0:192) @ W1 + b1)        -> overlay A rows 64..191
//   GEMM2: m   = hid @ W2 + b2                   -> overlay A rows 64..127
//   scatter: atomicAdd(g_agg[r], m)              (issued before GEMM3)
//   GEMM3: e_new = relu(A(0:128) @ We + be)      -> gmem
// All GEMMs use packed fma.rn.f32x2: warp -> column group, lane -> edge pair.
__global__ void __launch_bounds__(EK_THREADS, 1)
edge_kernel(const float* __restrict__ h, const float* __restrict__ e,
            const int* __restrict__ senders, const int* __restrict__ receivers,
            const float* __restrict__ W1, const float* __restrict__ b1,
            const float* __restrict__ W2, const float* __restrict__ b2,
            const float* __restrict__ We, const float* __restrict__ be,
            float* __restrict__ out_e)
{
    extern __shared__ float sm[];
    const int tid = threadIdx.x;

    // stage weights (L2 -> smem) once per block
    for (int i = tid; i < KIN * DH / 4; i += EK_THREADS)
        ((float4*)(sm + OFF_W1))[i] = ((const float4*)W1)[i];
    for (int i = tid; i < DH * D / 4; i += EK_THREADS)
        ((float4*)(sm + OFF_W2))[i] = ((const float4*)W2)[i];
    for (int i = tid; i < DH * D / 4; i += EK_THREADS)
        ((float4*)(sm + OFF_WE))[i] = ((const float4*)We)[i];
    if (tid < DH) sm[OFF_B1 + tid] = b1[tid];
    if (tid < D)  sm[OFF_B2 + tid] = b2[tid];
    else if (tid < 2 * D) sm[OFF_BE + tid - D] = be[tid - D];
    __syncthreads();

    // thread maps
    const int el   = tid >> 2;        // gather: edge 0..63
    const int part = tid & 3;         // gather: 16-float chunk
    const int wid  = tid >> 5;        // warp 0..7
    const int lane = tid & 31;
    const int el0  = 2 * lane;        // GEMM: edge pair base
    const int cb1  = wid * 16;        // GEMM1: 16-col group
    const int cb2  = wid * 8;         // GEMM2/3: 8-col group
    const int sj   = tid & 63;        // scatter: feature col
    const int sgrp = tid >> 6;        // scatter: edge group (16 edges)

    int* ridx = (int*)(sm + OFF_RIDX);

    const int n_tiles = N_EDGES / TILE_E;
    for (int tile = blockIdx.x; tile < n_tiles; tile += gridDim.x) {
        const int base = tile * TILE_E;

        // ---- gather (transposed K-major writes) ----
        {
            const int s = senders[base + el];
            const int r = receivers[base + el];
            if (part == 0) ridx[el] = r;
            const float4* ep = (const float4*)(e + (size_t)(base + el) * D) + part * 4;
            const float4* hs = (const float4*)(h + (size_t)s * D) + part * 4;
            const float4* hr = (const float4*)(h + (size_t)r * D) + part * 4;
            #pragma unroll
            for (int q = 0; q < 4; q++) {
                float4 v = ep[q];
                int k0 = part * 16 + q * 4;
                sm[OFF_A + (k0 + 0) * APAD + el] = v.x;
                sm[OFF_A + (k0 + 1) * APAD + el] = v.y;
                sm[OFF_A + (k0 + 2) * APAD + el] = v.z;
                sm[OFF_A + (k0 + 3) * APAD + el] = v.w;
            }
            #pragma unroll
            for (int q = 0; q < 4; q++) {
                float4 v = hs[q];
                int k0 = 64 + part * 16 + q * 4;
                sm[OFF_A + (k0 + 0) * APAD + el] = v.x;
                sm[OFF_A + (k0 + 1) * APAD + el] = v.y;
                sm[OFF_A + (k0 + 2) * APAD + el] = v.z;
                sm[OFF_A + (k0 + 3) * APAD + el] = v.w;
            }
            #pragma unroll
            for (int q = 0; q < 4; q++) {
                float4 v = hr[q];
                int k0 = 128 + part * 16 + q * 4;
                sm[OFF_A + (k0 + 0) * APAD + el] = v.x;
                sm[OFF_A + (k0 + 1) * APAD + el] = v.y;
                sm[OFF_A + (k0 + 2) * APAD + el] = v.z;
                sm[OFF_A + (k0 + 3) * APAD + el] = v.w;
            }
        }
        __syncthreads();

        // ---- GEMM1: [64,192] @ [192,128], packed f32x2, 2 edges x 16 cols ----
        {
            u64 acc[2][8];
            #pragma unroll
            for (int i = 0; i < 2; i++)
                #pragma unroll
                for (int j = 0; j < 8; j++) acc[i][j] = 0ull;

            const float* Arow = sm + OFF_A + el0;
            const float* Wrow = sm + OFF_W1 + cb1;
            #pragma unroll 4
            for (int k = 0; k < KIN; k++) {
                float2 a = *(const float2*)(Arow + k * APAD);
                u64 a0 = dupf(a.x), a1 = dupf(a.y);
                const u64* w2 = (const u64*)(Wrow + k * DH);   // 8 col-pairs
                #pragma unroll
                for (int j = 0; j < 8; j++) {
                    u64 w = w2[j];
                    fma2(acc[0][j], a0, w, acc[0][j]);
                    fma2(acc[1][j], a1, w, acc[1][j]);
                }
            }
            __syncthreads();
            #pragma unroll
            for (int i = 0; i < 2; i++) {
                #pragma unroll
                for (int j = 0; j < 8; j++) {
                    float lo, hi; unpack2(acc[i][j], lo, hi);
                    int c = cb1 + 2 * j;
                    sm[OFF_A + (64 + c)     * APAD + el0 + i] =
                        fmaxf(lo + sm[OFF_B1 + c],     0.f);
                    sm[OFF_A + (64 + c + 1) * APAD + el0 + i] =
                        fmaxf(hi + sm[OFF_B1 + c + 1], 0.f);
                }
            }
        }
        __syncthreads();

        // ---- GEMM2: [64,128] @ [128,64], packed f32x2, 2 edges x 8 cols ----
        {
            u64 acc[2][4];
            #pragma unroll
            for (int i = 0; i < 2; i++)
                #pragma unroll
                for (int j = 0; j < 4; j++) acc[i][j] = 0ull;

            const float* Arow = sm + OFF_A + 64 * APAD + el0;
            const float* Wrow = sm + OFF_W2 + cb2;
            #pragma unroll 4
            for (int k = 0; k < DH; k++) {
                float2 a = *(const float2*)(Arow + k * APAD);
                u64 a0 = dupf(a.x), a1 = dupf(a.y);
                const u64* w2 = (const u64*)(Wrow + k * D);    // 4 col-pairs
                #pragma unroll
                for (int j = 0; j < 4; j++) {
                    u64 w = w2[j];
                    fma2(acc[0][j], a0, w, acc[0][j]);
                    fma2(acc[1][j], a1, w, acc[1][j]);
                }
            }
            __syncthreads();
            #pragma unroll
            for (int i = 0; i < 2; i++) {
                #pragma unroll
                for (int j = 0; j < 4; j++) {
                    float lo, hi; unpack2(acc[i][j], lo, hi);
                    int c = cb2 + 2 * j;
                    sm[OFF_A + (64 + c)     * APAD + el0 + i] = lo + sm[OFF_B2 + c];
                    sm[OFF_A + (64 + c + 1) * APAD + el0 + i] = hi + sm[OFF_B2 + c + 1];
                }
            }
        }
        __syncthreads();

        // ---- scatter m into g_agg (fire-and-forget, overlaps GEMM3) ----
        #pragma unroll 4
        for (int ii = 0; ii < 16; ii++) {
            int els = sgrp * 16 + ii;
            int r = ridx[els];
            atomicAdd(&g_agg[(size_t)r * D + sj], sm[OFF_A + (64 + sj) * APAD + els]);
        }

        // ---- GEMM3: [64,128] @ [128,64] -> e_new, packed f32x2 ----
        {
            u64 acc[2][4];
            #pragma unroll
            for (int i = 0; i < 2; i++)
                #pragma unroll
                for (int j = 0; j < 4; j++) acc[i][j] = 0ull;

            const float* Arow = sm + OFF_A + el0;
            const float* Wrow = sm + OFF_WE + cb2;
            #pragma unroll 4
            for (int k = 0; k < DH; k++) {
                float2 a = *(const float2*)(Arow + k * APAD);
                u64 a0 = dupf(a.x), a1 = dupf(a.y);
                const u64* w2 = (const u64*)(Wrow + k * D);
                #pragma unroll
                for (int j = 0; j < 4; j++) {
                    u64 w = w2[j];
                    fma2(acc[0][j], a0, w, acc[0][j]);
                    fma2(acc[1][j], a1, w, acc[1][j]);
                }
            }
            #pragma unroll
            for (int i = 0; i < 2; i++) {
                float v[8];
                #pragma unroll
                for (int j = 0; j < 4; j++) {
                    float lo, hi; unpack2(acc[i][j], lo, hi);
                    int c = cb2 + 2 * j;
                    v[2 * j]     = fmaxf(lo + sm[OFF_BE + c],     0.f);
                    v[2 * j + 1] = fmaxf(hi + sm[OFF_BE + c + 1], 0.f);
                }
                float* dst = out_e + (size_t)(base + el0 + i) * D + cb2;
                *(float4*)(dst)     = make_float4(v[0], v[1], v[2], v[3]);
                *(float4*)(dst + 4) = make_float4(v[4], v[5], v[6], v[7]);
            }
        }
        __syncthreads();   // protect A / ridx before next tile's gather
    }
}

// ---------------- node kernel: h_new = relu([h | agg] @ W_node + b) ----------
#define NT    32
#define NPAD  36
#define NOFF_W 0
#define NOFF_B (NOFF_W + DH * D)      // 8192
#define NOFF_X (NOFF_B + D)           // 8256
#define SMEM_NODE_FLOATS (NOFF_X + DH * NPAD)
#define SMEM_NODE_BYTES  (SMEM_NODE_FLOATS * 4)

__global__ void __launch_bounds__(128)
node_kernel(const float* __restrict__ h,
            const float* __restrict__ Wn, const float* __restrict__ bn,
            float* __restrict__ out_h)
{
    extern __shared__ float sm[];
    const int tid = threadIdx.x;

    for (int i = tid; i < DH * D / 4; i += 128)
        ((float4*)(sm + NOFF_W))[i] = ((const float4*)Wn)[i];
    if (tid < D) sm[NOFF_B + tid] = bn[tid];
    __syncthreads();

    const int nl   = tid >> 2;   // 0..31
    const int part = tid & 3;
    const int ng   = tid >> 4;   // 0..7 (4 nodes)
    const int cgc  = tid & 15;   // 4 cols

    const int n_tiles = N_NODES / NT;
    for (int tile = blockIdx.x; tile < n_tiles; tile += gridDim.x) {
        const int base = tile * NT;
        // gather (contiguous rows, transposed K-major store)
        {
            const float4* hp = (const float4*)(h + (size_t)(base + nl) * D) + part * 4;
            const float4* ap = (const float4*)(g_agg + (size_t)(base + nl) * D) + part * 4;
            #pragma unroll
            for (int q = 0; q < 4; q++) {
                float4 v = hp[q];
                int k0 = part * 16 + q * 4;
                sm[NOFF_X + (k0 + 0) * NPAD + nl] = v.x;
                sm[NOFF_X + (k0 + 1) * NPAD + nl] = v.y;
                sm[NOFF_X + (k0 + 2) * NPAD + nl] = v.z;
                sm[NOFF_X + (k0 + 3) * NPAD + nl] = v.w;
            }
            #pragma unroll
            for (int q = 0; q < 4; q++) {
                float4 v = ap[q];
                int k0 = 64 + part * 16 + q * 4;
                sm[NOFF_X + (k0 + 0) * NPAD + nl] = v.x;
                sm[NOFF_X + (k0 + 1) * NPAD + nl] = v.y;
                sm[NOFF_X + (k0 + 2) * NPAD + nl] = v.z;
                sm[NOFF_X + (k0 + 3) * NPAD + nl] = v.w;
            }
        }
        __syncthreads();

        float acc[4][4];
        #pragma unroll
        for (int i = 0; i < 4; i++)
            #pragma unroll
            for (int j = 0; j < 4; j++) acc[i][j] = 0.f;

        const float* Xb = sm + NOFF_X + ng * 4;
        const float* Wb = sm + NOFF_W + cgc * 4;
        #pragma unroll 4
        for (int k = 0; k < DH; k++) {
            float4 a = *(const float4*)(Xb + k * NPAD);
            float4 w = *(const float4*)(Wb + k * D);
            float av[4] = {a.x, a.y, a.z, a.w};
            float wv[4] = {w.x, w.y, w.z, w.w};
            #pragma unroll
            for (int i = 0; i < 4; i++)
                #pragma unroll
                for (int j = 0; j < 4; j++)
                    acc[i][j] = fmaf(av[i], wv[j], acc[i][j]);
        }
        float bb[4];
        #pragma unroll
        for (int j = 0; j < 4; j++) bb[j] = sm[NOFF_B + cgc * 4 + j];
        #pragma unroll
        for (int i = 0; i < 4; i++) {
            float4 v;
            v.x = fmaxf(acc[i][0] + bb[0], 0.f);
            v.y = fmaxf(acc[i][1] + bb[1], 0.f);
            v.z = fmaxf(acc[i][2] + bb[2], 0.f);
            v.w = fmaxf(acc[i][3] + bb[3], 0.f);
            *(float4*)(out_h + (size_t)(base + ng * 4 + i) * D + cgc * 4) = v;
        }
        __syncthreads();
    }
}

// ---------------- launch -----------------------------------------------------
extern "C" void kernel_launch(void* const* d_in, const int* in_sizes, int n_in,
                              void* d_out, int out_size)
{
    const float* h        = (const float*)d_in[0];
    const float* e        = (const float*)d_in[1];
    const int*   senders  = (const int*)d_in[2];
    const int*   receivers= (const int*)d_in[3];
    const float* W1       = (const float*)d_in[4];
    const float* b1       = (const float*)d_in[5];
    const float* W2       = (const float*)d_in[6];
    const float* b2       = (const float*)d_in[7];
    const float* Wn       = (const float*)d_in[8];
    const float* bn       = (const float*)d_in[9];
    const float* We       = (const float*)d_in[10];
    const float* be       = (const float*)d_in[11];

    float* out_h = (float*)d_out;
    float* out_e = out_h + (size_t)N_NODES * D;

    cudaFuncSetAttribute(edge_kernel, cudaFuncAttributeMaxDynamicSharedMemorySize,
                         SMEM_EDGE_BYTES);
    cudaFuncSetAttribute(node_kernel, cudaFuncAttributeMaxDynamicSharedMemorySize,
                         SMEM_NODE_BYTES);

    zero_agg_kernel<<<(N_NODES * D / 4 + 255) / 256, 256>>>();
    edge_kernel<<<2960, EK_THREADS, SMEM_EDGE_BYTES>>>(
        h, e, senders, receivers, W1, b1, W2, b2, We, be, out_e);
    node_kernel<<<1480, 128, SMEM_NODE_BYTES>>>(h, Wn, bn, out_h);
}

// round 6
// speedup vs baseline: 2.1084x; 1.9301x over previous
#include <cuda_runtime.h>
#include <cstdint>

#define N_NODES 100000
#define N_EDGES 1600000
#define D       64
#define DH      128
#define KIN     192

#define TILE_E   64
#define N_TILES  (N_EDGES / TILE_E)   // 25000
#define EK_GRID  148
#define EK_THREADS 256

// ---------------- smem byte offsets (edge kernel) ----------------------------
#define OFF_PL    0          // planes: 2 x [96][64] floats = 49152
#define OFF_W1    49152      // [192][128] tf32 swizzled: 98304
#define OFF_W2    147456     // [128][64]: 32768
#define OFF_WE    180224     // [128][64]: 32768
#define OFF_BI1   212992     // 512
#define OFF_BI2   213504     // 256
#define OFF_BIE   213760     // 256
#define OFF_RIDX  214016     // 256
#define OFF_MF    214272     // m fp32 staging [64][65]: 16640
#define SMEM_EDGE_BYTES 230912

#define PLANE1 6144          // float offset of plane1

// ---------------- helpers ----------------------------------------------------
__device__ __forceinline__ uint32_t tf32c(float f) {
    uint32_t u; asm("cvt.rna.tf32.f32 %0, %1;" : "=r"(u) : "f"(f)); return u;
}
__device__ __forceinline__ int poffg(int gk, int e) {
    return (((gk >> 2) & 1) * PLANE1) + (((gk >> 3) * 4 + (gk & 3)) * 64)
         + (e ^ ((gk & 3) << 3));
}
__device__ __forceinline__ void mma8(float* c, const uint32_t* a, const uint32_t* b) {
    asm volatile(
        "mma.sync.aligned.m16n8k8.row.col.f32.tf32.tf32.f32 "
        "{%0,%1,%2,%3}, {%4,%5,%6,%7}, {%8,%9}, {%0,%1,%2,%3};"
        : "+f"(c[0]), "+f"(c[1]), "+f"(c[2]), "+f"(c[3])
        : "r"(a[0]), "r"(a[1]), "r"(a[2]), "r"(a[3]), "r"(b[0]), "r"(b[1]));
}

// ---------------- scratch ----------------------------------------------------
__device__ float g_agg[(size_t)N_NODES * D];

__global__ void zero_agg_kernel() {
    size_t i = (size_t)blockIdx.x * blockDim.x + threadIdx.x;
    size_t n4 = (size_t)N_NODES * D / 4;
    if (i < n4) ((float4*)g_agg)[i] = make_float4(0.f, 0.f, 0.f, 0.f);
}

// ---------------- fused edge kernel (tf32 mma.sync) --------------------------
__global__ void __launch_bounds__(EK_THREADS, 1)
edge_kernel(const float* __restrict__ h, const float* __restrict__ e,
            const int* __restrict__ senders, const int* __restrict__ receivers,
            const float* __restrict__ W1, const float* __restrict__ b1,
            const float* __restrict__ W2, const float* __restrict__ b2,
            const float* __restrict__ We, const float* __restrict__ be,
            float* __restrict__ out_e)
{
    extern __shared__ char smc[];
    uint32_t* PLu = (uint32_t*)(smc + OFF_PL);
    uint32_t* W1u = (uint32_t*)(smc + OFF_W1);
    uint32_t* W2u = (uint32_t*)(smc + OFF_W2);
    uint32_t* WEu = (uint32_t*)(smc + OFF_WE);
    float* bi1 = (float*)(smc + OFF_BI1);
    float* bi2 = (float*)(smc + OFF_BI2);
    float* bie = (float*)(smc + OFF_BIE);
    int*   ridx = (int*)(smc + OFF_RIDX);
    float* mf   = (float*)(smc + OFF_MF);

    const int tid  = threadIdx.x;
    const int w    = tid >> 5;
    const int lane = tid & 31;
    const int g    = lane >> 2;
    const int tig  = lane & 3;
    const int swz  = tig << 3;

    // ---- stage weights (tf32, XOR-8 col swizzle keyed on k&3) + biases ------
    for (int i = tid; i < KIN * DH; i += EK_THREADS) {
        int k = i >> 7, n = i & 127;
        W1u[k * 128 + (n ^ ((k & 3) << 3))] = tf32c(W1[i]);
    }
    for (int i = tid; i < DH * D; i += EK_THREADS) {
        int k = i >> 6, n = i & 63;
        W2u[k * 64 + (n ^ ((k & 3) << 3))] = tf32c(W2[i]);
        WEu[k * 64 + (n ^ ((k & 3) << 3))] = tf32c(We[i]);
    }
    if (tid < DH) bi1[tid] = b1[tid];
    if (tid < D)  bi2[tid] = b2[tid];
    else if (tid < 2 * D) bie[tid - D] = be[tid - D];

    const int c0w1 = (w & 3) * 32;
    const int e0w1 = (w >> 2) * 32;
    const int wl   = w & 3;
    const int c0w2 = (wl & 1) * 32;
    const int e0w2 = (wl >> 1) * 32;

    for (int tile = blockIdx.x; tile < N_TILES; tile += gridDim.x) {
        const int base = tile * TILE_E;
        __syncthreads();   // S0

        // ================= gather: [e|hs|hr] -> planes (tf32) ================
        {
            const int el = tid & 63;
            const int p  = tid >> 6;
            const int sI = senders[base + el];
            const int rI = receivers[base + el];
            if (p == 0) ridx[el] = rI;
            const float* s0 = e + (size_t)(base + el) * D;
            const float* s1 = h + (size_t)sI * D;
            const float* s2 = h + (size_t)rI * D;
            #pragma unroll
            for (int s3 = 0; s3 < 3; s3++) {
                const float4* sp =
                    (const float4*)(s3 == 0 ? s0 : (s3 == 1 ? s1 : s2)) + p * 4;
                #pragma unroll
                for (int q = 0; q < 4; q++) {
                    float4 v = sp[q];
                    int gk = s3 * 64 + p * 16 + q * 4;
                    PLu[poffg(gk + 0, el)] = tf32c(v.x);
                    PLu[poffg(gk + 1, el)] = tf32c(v.y);
                    PLu[poffg(gk + 2, el)] = tf32c(v.z);
                    PLu[poffg(gk + 3, el)] = tf32c(v.w);
                }
            }
        }
        __syncthreads();   // S1

        // ================= GEMM1: hid[128c x 64e] ============================
        float acc1[2][4][4];
        #pragma unroll
        for (int mt = 0; mt < 2; mt++)
            #pragma unroll
            for (int nt = 0; nt < 4; nt++)
                #pragma unroll
                for (int q = 0; q < 4; q++) acc1[mt][nt][q] = 0.f;

        #pragma unroll 2
        for (int kt = 0; kt < 24; kt++) {
            const int k0 = kt * 8;
            uint32_t av[2][4];
            #pragma unroll
            for (int mt = 0; mt < 2; mt++) {
                int c  = c0w1 + 16 * mt + g;
                int cs0 = c ^ swz, cs1 = (c + 8) ^ swz;
                av[mt][0] = W1u[(k0 + tig) * 128 + cs0];
                av[mt][1] = W1u[(k0 + tig) * 128 + cs1];
                av[mt][2] = W1u[(k0 + tig + 4) * 128 + cs0];
                av[mt][3] = W1u[(k0 + tig + 4) * 128 + cs1];
            }
            uint32_t bv[4][2];
            const int brow = (kt * 4 + tig) * 64;
            #pragma unroll
            for (int nt = 0; nt < 4; nt++) {
                int col = (e0w1 + nt * 8 + g) ^ swz;
                bv[nt][0] = PLu[brow + col];
                bv[nt][1] = PLu[brow + col + PLANE1];
            }
            #pragma unroll
            for (int mt = 0; mt < 2; mt++)
                #pragma unroll
                for (int nt = 0; nt < 4; nt++)
                    mma8(acc1[mt][nt], av[mt], bv[nt]);
        }
        __syncthreads();   // S2

        // ===== epilogue1: hid = relu(acc+b1) -> planes gk 64..191 ============
        #pragma unroll
        for (int mt = 0; mt < 2; mt++)
            #pragma unroll
            for (int nt = 0; nt < 4; nt++) {
                int cA = c0w1 + 16 * mt + g;
                int eA = e0w1 + 8 * nt + 2 * tig;
                float v0 = fmaxf(acc1[mt][nt][0] + bi1[cA], 0.f);
                float v1 = fmaxf(acc1[mt][nt][1] + bi1[cA], 0.f);
                float v2 = fmaxf(acc1[mt][nt][2] + bi1[cA + 8], 0.f);
                float v3 = fmaxf(acc1[mt][nt][3] + bi1[cA + 8], 0.f);
                PLu[poffg(64 + cA,     eA)]     = tf32c(v0);
                PLu[poffg(64 + cA,     eA + 1)] = tf32c(v1);
                PLu[poffg(64 + cA + 8, eA)]     = tf32c(v2);
                PLu[poffg(64 + cA + 8, eA + 1)] = tf32c(v3);
            }
        __syncthreads();   // S3

        // ===== warps0-3: GEMM2 | warps4-7: GEMM3a ============================
        float acc2[2][4][4];
        #pragma unroll
        for (int mt = 0; mt < 2; mt++)
            #pragma unroll
            for (int nt = 0; nt < 4; nt++)
                #pragma unroll
                for (int q = 0; q < 4; q++) acc2[mt][nt][q] = 0.f;

        if (w < 4) {
            #pragma unroll 2
            for (int kt = 0; kt < 16; kt++) {
                const int k0 = kt * 8;
                uint32_t av[2][4];
                #pragma unroll
                for (int mt = 0; mt < 2; mt++) {
                    int c = c0w2 + 16 * mt + g;
                    int cs0 = c ^ swz, cs1 = (c + 8) ^ swz;
                    av[mt][0] = W2u[(k0 + tig) * 64 + cs0];
                    av[mt][1] = W2u[(k0 + tig) * 64 + cs1];
                    av[mt][2] = W2u[(k0 + tig + 4) * 64 + cs0];
                    av[mt][3] = W2u[(k0 + tig + 4) * 64 + cs1];
                }
                uint32_t bv[4][2];
                const int brow = ((8 + kt) * 4 + tig) * 64;
                #pragma unroll
                for (int nt = 0; nt < 4; nt++) {
                    int col = (e0w2 + nt * 8 + g) ^ swz;
                    bv[nt][0] = PLu[brow + col];
                    bv[nt][1] = PLu[brow + col + PLANE1];
                }
                #pragma unroll
                for (int mt = 0; mt < 2; mt++)
                    #pragma unroll
                    for (int nt = 0; nt < 4; nt++)
                        mma8(acc2[mt][nt], av[mt], bv[nt]);
            }
        } else {
            #pragma unroll 2
            for (int kt = 0; kt < 8; kt++) {
                const int k0 = kt * 8;
                uint32_t av[2][4];
                #pragma unroll
                for (int mt = 0; mt < 2; mt++) {
                    int c = c0w2 + 16 * mt + g;
                    int cs0 = c ^ swz, cs1 = (c + 8) ^ swz;
                    av[mt][0] = WEu[(k0 + tig) * 64 + cs0];
                    av[mt][1] = WEu[(k0 + tig) * 64 + cs1];
                    av[mt][2] = WEu[(k0 + tig + 4) * 64 + cs0];
                    av[mt][3] = WEu[(k0 + tig + 4) * 64 + cs1];
                }
                uint32_t bv[4][2];
                const int brow = (kt * 4 + tig) * 64;
                #pragma unroll
                for (int nt = 0; nt < 4; nt++) {
                    int col = (e0w2 + nt * 8 + g) ^ swz;
                    bv[nt][0] = PLu[brow + col];
                    bv[nt][1] = PLu[brow + col + PLANE1];
                }
                #pragma unroll
                for (int mt = 0; mt < 2; mt++)
                    #pragma unroll
                    for (int nt = 0; nt < 4; nt++)
                        mma8(acc2[mt][nt], av[mt], bv[nt]);
            }
        }
        __syncthreads();   // S4

        // ===== epilogue2 (w0-3): m -> planes (tf32) + mf (fp32) ==============
        if (w < 4) {
            #pragma unroll
            for (int mt = 0; mt < 2; mt++)
                #pragma unroll
                for (int nt = 0; nt < 4; nt++) {
                    int cA = c0w2 + 16 * mt + g;
                    int eA = e0w2 + 8 * nt + 2 * tig;
                    float v0 = acc2[mt][nt][0] + bi2[cA];
                    float v1 = acc2[mt][nt][1] + bi2[cA];
                    float v2 = acc2[mt][nt][2] + bi2[cA + 8];
                    float v3 = acc2[mt][nt][3] + bi2[cA + 8];
                    PLu[poffg(64 + cA,     eA)]     = tf32c(v0);
                    PLu[poffg(64 + cA,     eA + 1)] = tf32c(v1);
                    PLu[poffg(64 + cA + 8, eA)]     = tf32c(v2);
                    PLu[poffg(64 + cA + 8, eA + 1)] = tf32c(v3);
                    mf[eA * 65 + cA]           = v0;
                    mf[(eA + 1) * 65 + cA]     = v1;
                    mf[eA * 65 + cA + 8]       = v2;
                    mf[(eA + 1) * 65 + cA + 8] = v3;
                }
        }
        __syncthreads();   // S5

        if (w >= 4) {
            // ===== GEMM3b: += m @ We[64:128] ================================
            #pragma unroll 2
            for (int kt = 0; kt < 8; kt++) {
                const int k0 = 64 + kt * 8;
                uint32_t av[2][4];
                #pragma unroll
                for (int mt = 0; mt < 2; mt++) {
                    int c = c0w2 + 16 * mt + g;
                    int cs0 = c ^ swz, cs1 = (c + 8) ^ swz;
                    av[mt][0] = WEu[(k0 + tig) * 64 + cs0];
                    av[mt][1] = WEu[(k0 + tig) * 64 + cs1];
                    av[mt][2] = WEu[(k0 + tig + 4) * 64 + cs0];
                    av[mt][3] = WEu[(k0 + tig + 4) * 64 + cs1];
                }
                uint32_t bv[4][2];
                const int brow = ((8 + kt) * 4 + tig) * 64;
                #pragma unroll
                for (int nt = 0; nt < 4; nt++) {
                    int col = (e0w2 + nt * 8 + g) ^ swz;
                    bv[nt][0] = PLu[brow + col];
                    bv[nt][1] = PLu[brow + col + PLANE1];
                }
                #pragma unroll
                for (int mt = 0; mt < 2; mt++)
                    #pragma unroll
                    for (int nt = 0; nt < 4; nt++)
                        mma8(acc2[mt][nt], av[mt], bv[nt]);
            }
            // ===== epilogue3: e_new = relu(acc+be) -> gmem ===================
            #pragma unroll
            for (int mt = 0; mt < 2; mt++)
                #pragma unroll
                for (int nt = 0; nt < 4; nt++) {
                    int cA = c0w2 + 16 * mt + g;
                    int eA = e0w2 + 8 * nt + 2 * tig;
                    float* d0 = out_e + (size_t)(base + eA) * D;
                    float* d1 = out_e + (size_t)(base + eA + 1) * D;
                    d0[cA]     = fmaxf(acc2[mt][nt][0] + bie[cA], 0.f);
                    d1[cA]     = fmaxf(acc2[mt][nt][1] + bie[cA], 0.f);
                    d0[cA + 8] = fmaxf(acc2[mt][nt][2] + bie[cA + 8], 0.f);
                    d1[cA + 8] = fmaxf(acc2[mt][nt][3] + bie[cA + 8], 0.f);
                }
        } else {
            // ===== scatter: atomicAdd m (fp32) into g_agg ====================
            const int el = tid & 63;
            const int hf = tid >> 6;
            const int r  = ridx[el];
            const float* mrow = mf + el * 65 + hf * 32;
            float* dstp = g_agg + (size_t)r * D + hf * 32;
            #pragma unroll 8
            for (int c = 0; c < 32; c++) atomicAdd(dstp + c, mrow[c]);
        }
    }
}

// ---------------- node kernel: h_new = relu([h | agg] @ W_node + b) ----------
#define NT    32
#define NPAD  36
#define NOFF_W 0
#define NOFF_B (NOFF_W + DH * D)
#define NOFF_X (NOFF_B + D)
#define SMEM_NODE_FLOATS (NOFF_X + DH * NPAD)
#define SMEM_NODE_BYTES  (SMEM_NODE_FLOATS * 4)

__global__ void __launch_bounds__(128)
node_kernel(const float* __restrict__ h,
            const float* __restrict__ Wn, const float* __restrict__ bn,
            float* __restrict__ out_h)
{
    extern __shared__ float sm[];
    const int tid = threadIdx.x;

    for (int i = tid; i < DH * D / 4; i += 128)
        ((float4*)(sm + NOFF_W))[i] = ((const float4*)Wn)[i];
    if (tid < D) sm[NOFF_B + tid] = bn[tid];
    __syncthreads();

    const int nl   = tid >> 2;
    const int part = tid & 3;
    const int ng   = tid >> 4;
    const int cgc  = tid & 15;

    const int n_tiles = N_NODES / NT;
    for (int tile = blockIdx.x; tile < n_tiles; tile += gridDim.x) {
        const int base = tile * NT;
        {
            const float4* hp = (const float4*)(h + (size_t)(base + nl) * D) + part * 4;
            const float4* ap = (const float4*)(g_agg + (size_t)(base + nl) * D) + part * 4;
            #pragma unroll
            for (int q = 0; q < 4; q++) {
                float4 v = hp[q];
                int k0 = part * 16 + q * 4;
                sm[NOFF_X + (k0 + 0) * NPAD + nl] = v.x;
                sm[NOFF_X + (k0 + 1) * NPAD + nl] = v.y;
                sm[NOFF_X + (k0 + 2) * NPAD + nl] = v.z;
                sm[NOFF_X + (k0 + 3) * NPAD + nl] = v.w;
            }
            #pragma unroll
            for (int q = 0; q < 4; q++) {
                float4 v = ap[q];
                int k0 = 64 + part * 16 + q * 4;
                sm[NOFF_X + (k0 + 0) * NPAD + nl] = v.x;
                sm[NOFF_X + (k0 + 1) * NPAD + nl] = v.y;
                sm[NOFF_X + (k0 + 2) * NPAD + nl] = v.z;
                sm[NOFF_X + (k0 + 3) * NPAD + nl] = v.w;
            }
        }
        __syncthreads();

        float acc[4][4];
        #pragma unroll
        for (int i = 0; i < 4; i++)
            #pragma unroll
            for (int j = 0; j < 4; j++) acc[i][j] = 0.f;

        const float* Xb = sm + NOFF_X + ng * 4;
        const float* Wb = sm + NOFF_W + cgc * 4;
        #pragma unroll 4
        for (int k = 0; k < DH; k++) {
            float4 a = *(const float4*)(Xb + k * NPAD);
            float4 wv4 = *(const float4*)(Wb + k * D);
            float av[4] = {a.x, a.y, a.z, a.w};
            float wv[4] = {wv4.x, wv4.y, wv4.z, wv4.w};
            #pragma unroll
            for (int i = 0; i < 4; i++)
                #pragma unroll
                for (int j = 0; j < 4; j++)
                    acc[i][j] = fmaf(av[i], wv[j], acc[i][j]);
        }
        float bb[4];
        #pragma unroll
        for (int j = 0; j < 4; j++) bb[j] = sm[NOFF_B + cgc * 4 + j];
        #pragma unroll
        for (int i = 0; i < 4; i++) {
            float4 v;
            v.x = fmaxf(acc[i][0] + bb[0], 0.f);
            v.y = fmaxf(acc[i][1] + bb[1], 0.f);
            v.z = fmaxf(acc[i][2] + bb[2], 0.f);
            v.w = fmaxf(acc[i][3] + bb[3], 0.f);
            *(float4*)(out_h + (size_t)(base + ng * 4 + i) * D + cgc * 4) = v;
        }
        __syncthreads();
    }
}

// ---------------- launch -----------------------------------------------------
extern "C" void kernel_launch(void* const* d_in, const int* in_sizes, int n_in,
                              void* d_out, int out_size)
{
    const float* h        = (const float*)d_in[0];
    const float* e        = (const float*)d_in[1];
    const int*   senders  = (const int*)d_in[2];
    const int*   receivers= (const int*)d_in[3];
    const float* W1       = (const float*)d_in[4];
    const float* b1       = (const float*)d_in[5];
    const float* W2       = (const float*)d_in[6];
    const float* b2       = (const float*)d_in[7];
    const float* Wn       = (const float*)d_in[8];
    const float* bn       = (const float*)d_in[9];
    const float* We       = (const float*)d_in[10];
    const float* be       = (const float*)d_in[11];

    float* out_h = (float*)d_out;
    float* out_e = out_h + (size_t)N_NODES * D;

    cudaFuncSetAttribute(edge_kernel, cudaFuncAttributeMaxDynamicSharedMemorySize,
                         SMEM_EDGE_BYTES);
    cudaFuncSetAttribute(node_kernel, cudaFuncAttributeMaxDynamicSharedMemorySize,
                         SMEM_NODE_BYTES);

    zero_agg_kernel<<<(N_NODES * D / 4 + 255) / 256, 256>>>();
    edge_kernel<<<EK_GRID, EK_THREADS, SMEM_EDGE_BYTES>>>(
        h, e, senders, receivers, W1, b1, W2, b2, We, be, out_e);
    node_kernel<<<1480, 128, SMEM_NODE_BYTES>>>(h, Wn, bn, out_h);
}

// round 7
// speedup vs baseline: 2.7056x; 1.2833x over previous
#include <cuda_runtime.h>
#include <cuda_fp16.h>
#include <cstdint>

#define N_NODES 100000
#define N_EDGES 1600000
#define D       64
#define DH      128
#define KIN     192

#define TILE_E   64
#define N_TILES  (N_EDGES / TILE_E)   // 25000
#define EK_GRID  148
#define EK_THREADS 256

// ---------------- smem byte offsets (edge kernel) ----------------------------
// planes: fp16x2 words PW[96][64]  (p = gk/2, col e XOR-swizzled by (p&3)<<3)
#define OFF_PL    0          // 96*64*4   = 24576
#define OFF_W1    24576      // W1^T fp16x2 [128 rows][100 words] = 51200
#define OFF_W2    75776      // W2^T [64][68] = 17408
#define OFF_WE    93184      // We^T [64][68] = 17408
#define OFF_BI1   110592     // 512
#define OFF_BI2   111104     // 256
#define OFF_BIE   111360     // 256
#define OFF_RIDX  111616     // 256
#define OFF_MF    111872     // m fp32 staging [64][65] = 16640
#define SMEM_EDGE_BYTES 128512

// ---------------- helpers ----------------------------------------------------
__device__ __forceinline__ uint32_t packh2(float lo, float hi) {
    uint32_t d;
    asm("cvt.rn.f16x2.f32 %0, %1, %2;" : "=r"(d) : "f"(hi), "f"(lo));
    return d;
}
__device__ __forceinline__ void mma16(float* c, const uint32_t* a, const uint32_t* b) {
    asm volatile(
        "mma.sync.aligned.m16n8k16.row.col.f32.f16.f16.f32 "
        "{%0,%1,%2,%3}, {%4,%5,%6,%7}, {%8,%9}, {%0,%1,%2,%3};"
        : "+f"(c[0]), "+f"(c[1]), "+f"(c[2]), "+f"(c[3])
        : "r"(a[0]), "r"(a[1]), "r"(a[2]), "r"(a[3]), "r"(b[0]), "r"(b[1]));
}

// ---------------- scratch ----------------------------------------------------
__device__ float g_agg[(size_t)N_NODES * D];

__global__ void zero_agg_kernel() {
    size_t i = (size_t)blockIdx.x * blockDim.x + threadIdx.x;
    size_t n4 = (size_t)N_NODES * D / 4;
    if (i < n4) ((float4*)g_agg)[i] = make_float4(0.f, 0.f, 0.f, 0.f);
}

// ---------------- fused edge kernel (fp16 m16n8k16 mma.sync) -----------------
__global__ void __launch_bounds__(EK_THREADS, 1)
edge_kernel(const float* __restrict__ h, const float* __restrict__ e,
            const int* __restrict__ senders, const int* __restrict__ receivers,
            const float* __restrict__ W1, const float* __restrict__ b1,
            const float* __restrict__ W2, const float* __restrict__ b2,
            const float* __restrict__ We, const float* __restrict__ be,
            float* __restrict__ out_e)
{
    extern __shared__ char smc[];
    uint32_t* PW  = (uint32_t*)(smc + OFF_PL);
    __half*   PHh = (__half*)(smc + OFF_PL);
    uint32_t* W1w = (uint32_t*)(smc + OFF_W1);
    uint32_t* W2w = (uint32_t*)(smc + OFF_W2);
    uint32_t* WEw = (uint32_t*)(smc + OFF_WE);
    float* bi1 = (float*)(smc + OFF_BI1);
    float* bi2 = (float*)(smc + OFF_BI2);
    float* bie = (float*)(smc + OFF_BIE);
    int*   ridx = (int*)(smc + OFF_RIDX);
    float* mf   = (float*)(smc + OFF_MF);

    const int tid  = threadIdx.x;
    const int w    = tid >> 5;
    const int lane = tid & 31;
    const int g    = lane >> 2;
    const int tig  = lane & 3;
    const int swz  = tig << 3;

    // ---- stage weights in fp16x2 fragment order + biases --------------------
    // W1h[c][k2] = pack(W1[2k2][c], W1[2k2+1][c]),  row pad 96->100 words
    for (int i = tid; i < DH * (KIN / 2); i += EK_THREADS) {
        int c = i / 96, k2 = i % 96;
        W1w[c * 100 + k2] = packh2(W1[(2 * k2) * DH + c], W1[(2 * k2 + 1) * DH + c]);
    }
    for (int i = tid; i < D * (DH / 2); i += EK_THREADS) {   // 64 rows x 64 words
        int c = i >> 6, k2 = i & 63;
        W2w[c * 68 + k2] = packh2(W2[(2 * k2) * D + c], W2[(2 * k2 + 1) * D + c]);
        WEw[c * 68 + k2] = packh2(We[(2 * k2) * D + c], We[(2 * k2 + 1) * D + c]);
    }
    if (tid < DH) bi1[tid] = b1[tid];
    if (tid < D)  bi2[tid] = b2[tid];
    else if (tid < 2 * D) bie[tid - D] = be[tid - D];

    const int c0w1 = (w & 3) * 32;
    const int e0w1 = (w >> 2) * 32;
    const int wl   = w & 3;
    const int c0w2 = (wl & 1) * 32;
    const int e0w2 = (wl >> 1) * 32;

    for (int tile = blockIdx.x; tile < N_TILES; tile += gridDim.x) {
        const int base = tile * TILE_E;
        __syncthreads();   // S0

        // ================= gather: [e|hs|hr] -> planes (fp16x2) ==============
        {
            const int el = tid & 63;
            const int p4 = tid >> 6;
            const int sI = senders[base + el];
            const int rI = receivers[base + el];
            if (p4 == 0) ridx[el] = rI;
            const float* s0 = e + (size_t)(base + el) * D;
            const float* s1 = h + (size_t)sI * D;
            const float* s2 = h + (size_t)rI * D;
            #pragma unroll
            for (int s3 = 0; s3 < 3; s3++) {
                const float4* sp =
                    (const float4*)(s3 == 0 ? s0 : (s3 == 1 ? s1 : s2)) + p4 * 4;
                #pragma unroll
                for (int q = 0; q < 4; q++) {
                    float4 v = sp[q];
                    int p = s3 * 32 + p4 * 8 + q * 2;      // gk = 2p
                    PW[p * 64 + (el ^ ((p & 3) << 3))]             = packh2(v.x, v.y);
                    PW[(p + 1) * 64 + (el ^ (((p + 1) & 3) << 3))] = packh2(v.z, v.w);
                }
            }
        }
        __syncthreads();   // S1

        // ================= GEMM1: hid[128c x 64e], 12 K-steps of 16 ==========
        float acc1[2][4][4];
        #pragma unroll
        for (int mt = 0; mt < 2; mt++)
            #pragma unroll
            for (int nt = 0; nt < 4; nt++)
                #pragma unroll
                for (int q = 0; q < 4; q++) acc1[mt][nt][q] = 0.f;

        #pragma unroll 2
        for (int kt = 0; kt < 12; kt++) {
            const int k8 = kt * 8;
            uint32_t av[2][4];
            #pragma unroll
            for (int mt = 0; mt < 2; mt++) {
                int r = c0w1 + 16 * mt + g;
                av[mt][0] = W1w[r * 100 + k8 + tig];
                av[mt][1] = W1w[(r + 8) * 100 + k8 + tig];
                av[mt][2] = W1w[r * 100 + k8 + tig + 4];
                av[mt][3] = W1w[(r + 8) * 100 + k8 + tig + 4];
            }
            uint32_t bv[4][2];
            const int p0 = k8 + tig;
            #pragma unroll
            for (int nt = 0; nt < 4; nt++) {
                int es = (e0w1 + nt * 8 + g) ^ swz;
                bv[nt][0] = PW[p0 * 64 + es];
                bv[nt][1] = PW[(p0 + 4) * 64 + es];
            }
            #pragma unroll
            for (int mt = 0; mt < 2; mt++)
                #pragma unroll
                for (int nt = 0; nt < 4; nt++)
                    mma16(acc1[mt][nt], av[mt], bv[nt]);
        }
        __syncthreads();   // S2

        // ===== epilogue1: hid = relu(acc+b1) -> planes p 32..95 (fp16) =======
        #pragma unroll
        for (int mt = 0; mt < 2; mt++)
            #pragma unroll
            for (int nt = 0; nt < 4; nt++) {
                int cA = c0w1 + 16 * mt + g;
                int eA = e0w1 + 8 * nt + 2 * tig;
                float v0 = fmaxf(acc1[mt][nt][0] + bi1[cA], 0.f);
                float v1 = fmaxf(acc1[mt][nt][1] + bi1[cA], 0.f);
                float v2 = fmaxf(acc1[mt][nt][2] + bi1[cA + 8], 0.f);
                float v3 = fmaxf(acc1[mt][nt][3] + bi1[cA + 8], 0.f);
                int pA = 32 + (cA >> 1);
                int sub = cA & 1;
                int sw0 = (pA & 3) << 3;
                int esA = eA ^ sw0, esB = (eA + 1) ^ sw0;
                PHh[2 * (pA * 64 + esA) + sub]       = __float2half_rn(v0);
                PHh[2 * (pA * 64 + esB) + sub]       = __float2half_rn(v1);
                PHh[2 * ((pA + 4) * 64 + esA) + sub] = __float2half_rn(v2);
                PHh[2 * ((pA + 4) * 64 + esB) + sub] = __float2half_rn(v3);
            }
        __syncthreads();   // S3

        // ===== warps0-3: GEMM2 (m = hid @ W2) | warps4-7: GEMM3a (e-part) ====
        float acc2[2][4][4];
        #pragma unroll
        for (int mt = 0; mt < 2; mt++)
            #pragma unroll
            for (int nt = 0; nt < 4; nt++)
                #pragma unroll
                for (int q = 0; q < 4; q++) acc2[mt][nt][q] = 0.f;

        if (w < 4) {
            #pragma unroll 2
            for (int kt = 0; kt < 8; kt++) {          // hid: p = 32 + k2
                const int k8 = kt * 8;
                uint32_t av[2][4];
                #pragma unroll
                for (int mt = 0; mt < 2; mt++) {
                    int r = c0w2 + 16 * mt + g;
                    av[mt][0] = W2w[r * 68 + k8 + tig];
                    av[mt][1] = W2w[(r + 8) * 68 + k8 + tig];
                    av[mt][2] = W2w[r * 68 + k8 + tig + 4];
                    av[mt][3] = W2w[(r + 8) * 68 + k8 + tig + 4];
                }
                uint32_t bv[4][2];
                const int p0 = 32 + k8 + tig;
                #pragma unroll
                for (int nt = 0; nt < 4; nt++) {
                    int es = (e0w2 + nt * 8 + g) ^ swz;
                    bv[nt][0] = PW[p0 * 64 + es];
                    bv[nt][1] = PW[(p0 + 4) * 64 + es];
                }
                #pragma unroll
                for (int mt = 0; mt < 2; mt++)
                    #pragma unroll
                    for (int nt = 0; nt < 4; nt++)
                        mma16(acc2[mt][nt], av[mt], bv[nt]);
            }
        } else {
            #pragma unroll 2
            for (int kt = 0; kt < 4; kt++) {          // e-part: p = k2
                const int k8 = kt * 8;
                uint32_t av[2][4];
                #pragma unroll
                for (int mt = 0; mt < 2; mt++) {
                    int r = c0w2 + 16 * mt + g;
                    av[mt][0] = WEw[r * 68 + k8 + tig];
                    av[mt][1] = WEw[(r + 8) * 68 + k8 + tig];
                    av[mt][2] = WEw[r * 68 + k8 + tig + 4];
                    av[mt][3] = WEw[(r + 8) * 68 + k8 + tig + 4];
                }
                uint32_t bv[4][2];
                const int p0 = k8 + tig;
                #pragma unroll
                for (int nt = 0; nt < 4; nt++) {
                    int es = (e0w2 + nt * 8 + g) ^ swz;
                    bv[nt][0] = PW[p0 * 64 + es];
                    bv[nt][1] = PW[(p0 + 4) * 64 + es];
                }
                #pragma unroll
                for (int mt = 0; mt < 2; mt++)
                    #pragma unroll
                    for (int nt = 0; nt < 4; nt++)
                        mma16(acc2[mt][nt], av[mt], bv[nt]);
            }
        }
        __syncthreads();   // S4

        // ===== epilogue2 (w0-3): m -> planes p 32..63 (fp16) + mf (fp32) =====
        if (w < 4) {
            #pragma unroll
            for (int mt = 0; mt < 2; mt++)
                #pragma unroll
                for (int nt = 0; nt < 4; nt++) {
                    int cA = c0w2 + 16 * mt + g;
                    int eA = e0w2 + 8 * nt + 2 * tig;
                    float v0 = acc2[mt][nt][0] + bi2[cA];
                    float v1 = acc2[mt][nt][1] + bi2[cA];
                    float v2 = acc2[mt][nt][2] + bi2[cA + 8];
                    float v3 = acc2[mt][nt][3] + bi2[cA + 8];
                    int pA = 32 + (cA >> 1);
                    int sub = cA & 1;
                    int sw0 = (pA & 3) << 3;
                    int esA = eA ^ sw0, esB = (eA + 1) ^ sw0;
                    PHh[2 * (pA * 64 + esA) + sub]       = __float2half_rn(v0);
                    PHh[2 * (pA * 64 + esB) + sub]       = __float2half_rn(v1);
                    PHh[2 * ((pA + 4) * 64 + esA) + sub] = __float2half_rn(v2);
                    PHh[2 * ((pA + 4) * 64 + esB) + sub] = __float2half_rn(v3);
                    mf[eA * 65 + cA]           = v0;
                    mf[(eA + 1) * 65 + cA]     = v1;
                    mf[eA * 65 + cA + 8]       = v2;
                    mf[(eA + 1) * 65 + cA + 8] = v3;
                }
        }
        __syncthreads();   // S5

        if (w >= 4) {
            // ===== GEMM3b: += m @ We[64:128]  (m at p = k2, 32..63) ==========
            #pragma unroll 2
            for (int kt = 4; kt < 8; kt++) {
                const int k8 = kt * 8;
                uint32_t av[2][4];
                #pragma unroll
                for (int mt = 0; mt < 2; mt++) {
                    int r = c0w2 + 16 * mt + g;
                    av[mt][0] = WEw[r * 68 + k8 + tig];
                    av[mt][1] = WEw[(r + 8) * 68 + k8 + tig];
                    av[mt][2] = WEw[r * 68 + k8 + tig + 4];
                    av[mt][3] = WEw[(r + 8) * 68 + k8 + tig + 4];
                }
                uint32_t bv[4][2];
                const int p0 = k8 + tig;
                #pragma unroll
                for (int nt = 0; nt < 4; nt++) {
                    int es = (e0w2 + nt * 8 + g) ^ swz;
                    bv[nt][0] = PW[p0 * 64 + es];
                    bv[nt][1] = PW[(p0 + 4) * 64 + es];
                }
                #pragma unroll
                for (int mt = 0; mt < 2; mt++)
                    #pragma unroll
                    for (int nt = 0; nt < 4; nt++)
                        mma16(acc2[mt][nt], av[mt], bv[nt]);
            }
            // ===== epilogue3: e_new = relu(acc+be) -> gmem ===================
            #pragma unroll
            for (int mt = 0; mt < 2; mt++)
                #pragma unroll
                for (int nt = 0; nt < 4; nt++) {
                    int cA = c0w2 + 16 * mt + g;
                    int eA = e0w2 + 8 * nt + 2 * tig;
                    float* d0 = out_e + (size_t)(base + eA) * D;
                    float* d1 = out_e + (size_t)(base + eA + 1) * D;
                    d0[cA]     = fmaxf(acc2[mt][nt][0] + bie[cA], 0.f);
                    d1[cA]     = fmaxf(acc2[mt][nt][1] + bie[cA], 0.f);
                    d0[cA + 8] = fmaxf(acc2[mt][nt][2] + bie[cA + 8], 0.f);
                    d1[cA + 8] = fmaxf(acc2[mt][nt][3] + bie[cA + 8], 0.f);
                }
        } else {
            // ===== scatter: atomicAdd m (fp32) into g_agg ====================
            const int el = tid & 63;
            const int hf = tid >> 6;
            const int r  = ridx[el];
            const float* mrow = mf + el * 65 + hf * 32;
            float* dstp = g_agg + (size_t)r * D + hf * 32;
            #pragma unroll 8
            for (int c = 0; c < 32; c++) atomicAdd(dstp + c, mrow[c]);
        }
    }
}

// ---------------- node kernel: h_new = relu([h | agg] @ W_node + b) ----------
#define NT    32
#define NPAD  36
#define NOFF_W 0
#define NOFF_B (NOFF_W + DH * D)
#define NOFF_X (NOFF_B + D)
#define SMEM_NODE_FLOATS (NOFF_X + DH * NPAD)
#define SMEM_NODE_BYTES  (SMEM_NODE_FLOATS * 4)

__global__ void __launch_bounds__(128)
node_kernel(const float* __restrict__ h,
            const float* __restrict__ Wn, const float* __restrict__ bn,
            float* __restrict__ out_h)
{
    extern __shared__ float sm[];
    const int tid = threadIdx.x;

    for (int i = tid; i < DH * D / 4; i += 128)
        ((float4*)(sm + NOFF_W))[i] = ((const float4*)Wn)[i];
    if (tid < D) sm[NOFF_B + tid] = bn[tid];
    __syncthreads();

    const int nl   = tid >> 2;
    const int part = tid & 3;
    const int ng   = tid >> 4;
    const int cgc  = tid & 15;

    const int n_tiles = N_NODES / NT;
    for (int tile = blockIdx.x; tile < n_tiles; tile += gridDim.x) {
        const int base = tile * NT;
        {
            const float4* hp = (const float4*)(h + (size_t)(base + nl) * D) + part * 4;
            const float4* ap = (const float4*)(g_agg + (size_t)(base + nl) * D) + part * 4;
            #pragma unroll
            for (int q = 0; q < 4; q++) {
                float4 v = hp[q];
                int k0 = part * 16 + q * 4;
                sm[NOFF_X + (k0 + 0) * NPAD + nl] = v.x;
                sm[NOFF_X + (k0 + 1) * NPAD + nl] = v.y;
                sm[NOFF_X + (k0 + 2) * NPAD + nl] = v.z;
                sm[NOFF_X + (k0 + 3) * NPAD + nl] = v.w;
            }
            #pragma unroll
            for (int q = 0; q < 4; q++) {
                float4 v = ap[q];
                int k0 = 64 + part * 16 + q * 4;
                sm[NOFF_X + (k0 + 0) * NPAD + nl] = v.x;
                sm[NOFF_X + (k0 + 1) * NPAD + nl] = v.y;
                sm[NOFF_X + (k0 + 2) * NPAD + nl] = v.z;
                sm[NOFF_X + (k0 + 3) * NPAD + nl] = v.w;
            }
        }
        __syncthreads();

        float acc[4][4];
        #pragma unroll
        for (int i = 0; i < 4; i++)
            #pragma unroll
            for (int j = 0; j < 4; j++) acc[i][j] = 0.f;

        const float* Xb = sm + NOFF_X + ng * 4;
        const float* Wb = sm + NOFF_W + cgc * 4;
        #pragma unroll 4
        for (int k = 0; k < DH; k++) {
            float4 a = *(const float4*)(Xb + k * NPAD);
            float4 wv4 = *(const float4*)(Wb + k * D);
            float av[4] = {a.x, a.y, a.z, a.w};
            float wv[4] = {wv4.x, wv4.y, wv4.z, wv4.w};
            #pragma unroll
            for (int i = 0; i < 4; i++)
                #pragma unroll
                for (int j = 0; j < 4; j++)
                    acc[i][j] = fmaf(av[i], wv[j], acc[i][j]);
        }
        float bb[4];
        #pragma unroll
        for (int j = 0; j < 4; j++) bb[j] = sm[NOFF_B + cgc * 4 + j];
        #pragma unroll
        for (int i = 0; i < 4; i++) {
            float4 v;
            v.x = fmaxf(acc[i][0] + bb[0], 0.f);
            v.y = fmaxf(acc[i][1] + bb[1], 0.f);
            v.z = fmaxf(acc[i][2] + bb[2], 0.f);
            v.w = fmaxf(acc[i][3] + bb[3], 0.f);
            *(float4*)(out_h + (size_t)(base + ng * 4 + i) * D + cgc * 4) = v;
        }
        __syncthreads();
    }
}

// ---------------- launch -----------------------------------------------------
extern "C" void kernel_launch(void* const* d_in, const int* in_sizes, int n_in,
                              void* d_out, int out_size)
{
    const float* h        = (const float*)d_in[0];
    const float* e        = (const float*)d_in[1];
    const int*   senders  = (const int*)d_in[2];
    const int*   receivers= (const int*)d_in[3];
    const float* W1       = (const float*)d_in[4];
    const float* b1       = (const float*)d_in[5];
    const float* W2       = (const float*)d_in[6];
    const float* b2       = (const float*)d_in[7];
    const float* Wn       = (const float*)d_in[8];
    const float* bn       = (const float*)d_in[9];
    const float* We       = (const float*)d_in[10];
    const float* be       = (const float*)d_in[11];

    float* out_h = (float*)d_out;
    float* out_e = out_h + (size_t)N_NODES * D;

    cudaFuncSetAttribute(edge_kernel, cudaFuncAttributeMaxDynamicSharedMemorySize,
                         SMEM_EDGE_BYTES);
    cudaFuncSetAttribute(node_kernel, cudaFuncAttributeMaxDynamicSharedMemorySize,
                         SMEM_NODE_BYTES);

    zero_agg_kernel<<<(N_NODES * D / 4 + 255) / 256, 256>>>();
    edge_kernel<<<EK_GRID, EK_THREADS, SMEM_EDGE_BYTES>>>(
        h, e, senders, receivers, W1, b1, W2, b2, We, be, out_e);
    node_kernel<<<1480, 128, SMEM_NODE_BYTES>>>(h, Wn, bn, out_h);
}

// round 8
// speedup vs baseline: 3.0981x; 1.1451x over previous
#include <cuda_runtime.h>
#include <cuda_fp16.h>
#include <cstdint>

#define N_NODES 100000
#define N_EDGES 1600000
#define D       64
#define DH      128
#define KIN     192

#define TILE_E   64
#define N_TILES  (N_EDGES / TILE_E)   // 25000
#define EK_GRID  148
#define EK_THREADS 512                // 2 groups x 256

// ---------------- smem byte offsets (edge kernel) ----------------------------
#define OFF_W1    0          // W1^T fp16x2 [128 rows][100 words] = 51200
#define OFF_W2    51200      // W2^T [64][68] = 17408
#define OFF_WE    68608      // We^T [64][68] = 17408
#define OFF_BI1   86016      // 512
#define OFF_BI2   86528      // 256
#define OFF_BIE   86784      // 256
#define OFF_GRP   87040      // 2 x group block
// group block: planes 24576 | mf 16640 | ridx 256  = 41472
#define GRP_BYTES 41472
#define GOFF_MF   24576
#define GOFF_RIDX 41216
#define SMEM_EDGE_BYTES (OFF_GRP + 2 * GRP_BYTES)   // 169984

// ---------------- helpers ----------------------------------------------------
__device__ __forceinline__ uint32_t packh2(float lo, float hi) {
    uint32_t d;
    asm("cvt.rn.f16x2.f32 %0, %1, %2;" : "=r"(d) : "f"(hi), "f"(lo));
    return d;
}
__device__ __forceinline__ void mma16(float* c, const uint32_t* a, const uint32_t* b) {
    asm volatile(
        "mma.sync.aligned.m16n8k16.row.col.f32.f16.f16.f32 "
        "{%0,%1,%2,%3}, {%4,%5,%6,%7}, {%8,%9}, {%0,%1,%2,%3};"
        : "+f"(c[0]), "+f"(c[1]), "+f"(c[2]), "+f"(c[3])
        : "r"(a[0]), "r"(a[1]), "r"(a[2]), "r"(a[3]), "r"(b[0]), "r"(b[1]));
}

// ---------------- scratch ----------------------------------------------------
__device__ float g_agg[(size_t)N_NODES * D];

__global__ void zero_agg_kernel() {
    size_t i = (size_t)blockIdx.x * blockDim.x + threadIdx.x;
    size_t n4 = (size_t)N_NODES * D / 4;
    if (i < n4) ((float4*)g_agg)[i] = make_float4(0.f, 0.f, 0.f, 0.f);
}

// ---------------- fused edge kernel (fp16 mma, 2 tile-groups/CTA) ------------
__global__ void __launch_bounds__(EK_THREADS, 1)
edge_kernel(const float* __restrict__ h, const float* __restrict__ e,
            const int* __restrict__ senders, const int* __restrict__ receivers,
            const float* __restrict__ W1, const float* __restrict__ b1,
            const float* __restrict__ W2, const float* __restrict__ b2,
            const float* __restrict__ We, const float* __restrict__ be,
            float* __restrict__ out_e)
{
    extern __shared__ char smc[];
    uint32_t* W1w = (uint32_t*)(smc + OFF_W1);
    uint32_t* W2w = (uint32_t*)(smc + OFF_W2);
    uint32_t* WEw = (uint32_t*)(smc + OFF_WE);
    float* bi1 = (float*)(smc + OFF_BI1);
    float* bi2 = (float*)(smc + OFF_BI2);
    float* bie = (float*)(smc + OFF_BIE);

    const int tid = threadIdx.x;

    // ---- stage shared weights (fp16x2 fragment order) + biases --------------
    for (int i = tid; i < DH * (KIN / 2); i += EK_THREADS) {
        int c = i / 96, k2 = i % 96;
        W1w[c * 100 + k2] = packh2(W1[(2 * k2) * DH + c], W1[(2 * k2 + 1) * DH + c]);
    }
    for (int i = tid; i < D * (DH / 2); i += EK_THREADS) {
        int c = i >> 6, k2 = i & 63;
        W2w[c * 68 + k2] = packh2(W2[(2 * k2) * D + c], W2[(2 * k2 + 1) * D + c]);
        WEw[c * 68 + k2] = packh2(We[(2 * k2) * D + c], We[(2 * k2 + 1) * D + c]);
    }
    if (tid < DH) bi1[tid] = b1[tid];
    if (tid < D)  bi2[tid] = b2[tid];
    else if (tid < 2 * D) bie[tid - D] = be[tid - D];
    __syncthreads();

    // ---- group-local state ---------------------------------------------------
    const int gi   = tid >> 8;          // group 0/1
    const int lt   = tid & 255;         // thread-in-group
    const int w    = lt >> 5;           // warp-in-group 0..7
    const int lane = lt & 31;
    const int g    = lane >> 2;
    const int tig  = lane & 3;
    const int swz  = tig << 3;

    char* gbase = smc + OFF_GRP + gi * GRP_BYTES;
    uint32_t* PW  = (uint32_t*)gbase;
    __half*   PHh = (__half*)gbase;
    float*    mf  = (float*)(gbase + GOFF_MF);
    int*      ridx= (int*)(gbase + GOFF_RIDX);

    const int c0w1 = (w & 3) * 32;
    const int e0w1 = (w >> 2) * 32;
    const int wl   = w & 3;
    const int c0w2 = (wl & 1) * 32;
    const int e0w2 = (wl >> 1) * 32;
    const int barid = gi + 1;

    #define BARG() asm volatile("bar.sync %0, 256;" :: "r"(barid) : "memory")

    for (int tile = blockIdx.x * 2 + gi; tile < N_TILES; tile += 2 * gridDim.x) {
        const int base = tile * TILE_E;
        BARG();   // S0: prev scatter/epi3 done; planes/mf/ridx reusable

        // ================= gather: [e|hs|hr] -> planes (fp16x2) ==============
        {
            const int el = lt & 63;
            const int p4 = lt >> 6;
            const int sI = senders[base + el];
            const int rI = receivers[base + el];
            if (p4 == 0) ridx[el] = rI;
            const float* s0 = e + (size_t)(base + el) * D;
            const float* s1 = h + (size_t)sI * D;
            const float* s2 = h + (size_t)rI * D;
            #pragma unroll
            for (int s3 = 0; s3 < 3; s3++) {
                const float4* sp =
                    (const float4*)(s3 == 0 ? s0 : (s3 == 1 ? s1 : s2)) + p4 * 4;
                #pragma unroll
                for (int q = 0; q < 4; q++) {
                    float4 v = sp[q];
                    int p = s3 * 32 + p4 * 8 + q * 2;
                    PW[p * 64 + ((el) ^ ((p & 3) << 3))]           = packh2(v.x, v.y);
                    PW[(p + 1) * 64 + ((el) ^ (((p + 1) & 3) << 3))] = packh2(v.z, v.w);
                }
            }
        }
        BARG();   // S1

        // ================= GEMM1: hid[128c x 64e] ============================
        float acc1[2][4][4];
        #pragma unroll
        for (int mt = 0; mt < 2; mt++)
            #pragma unroll
            for (int nt = 0; nt < 4; nt++)
                #pragma unroll
                for (int q = 0; q < 4; q++) acc1[mt][nt][q] = 0.f;

        #pragma unroll 2
        for (int kt = 0; kt < 12; kt++) {
            const int k8 = kt * 8;
            uint32_t av[2][4];
            #pragma unroll
            for (int mt = 0; mt < 2; mt++) {
                int r = c0w1 + 16 * mt + g;
                av[mt][0] = W1w[r * 100 + k8 + tig];
                av[mt][1] = W1w[(r + 8) * 100 + k8 + tig];
                av[mt][2] = W1w[r * 100 + k8 + tig + 4];
                av[mt][3] = W1w[(r + 8) * 100 + k8 + tig + 4];
            }
            uint32_t bv[4][2];
            const int p0 = k8 + tig;
            #pragma unroll
            for (int nt = 0; nt < 4; nt++) {
                int es = (e0w1 + nt * 8 + g) ^ swz;
                bv[nt][0] = PW[p0 * 64 + es];
                bv[nt][1] = PW[(p0 + 4) * 64 + es];
            }
            #pragma unroll
            for (int mt = 0; mt < 2; mt++)
                #pragma unroll
                for (int nt = 0; nt < 4; nt++)
                    mma16(acc1[mt][nt], av[mt], bv[nt]);
        }
        BARG();   // S2

        // ===== epilogue1: hid = relu(acc+b1) -> planes p 32..95 (fp16) =======
        #pragma unroll
        for (int mt = 0; mt < 2; mt++)
            #pragma unroll
            for (int nt = 0; nt < 4; nt++) {
                int cA = c0w1 + 16 * mt + g;
                int eA = e0w1 + 8 * nt + 2 * tig;
                float v0 = fmaxf(acc1[mt][nt][0] + bi1[cA], 0.f);
                float v1 = fmaxf(acc1[mt][nt][1] + bi1[cA], 0.f);
                float v2 = fmaxf(acc1[mt][nt][2] + bi1[cA + 8], 0.f);
                float v3 = fmaxf(acc1[mt][nt][3] + bi1[cA + 8], 0.f);
                int pA = 32 + (cA >> 1);
                int sub = cA & 1;
                int sw0 = (pA & 3) << 3;
                int esA = eA ^ sw0, esB = (eA + 1) ^ sw0;
                PHh[2 * (pA * 64 + esA) + sub]       = __float2half_rn(v0);
                PHh[2 * (pA * 64 + esB) + sub]       = __float2half_rn(v1);
                PHh[2 * ((pA + 4) * 64 + esA) + sub] = __float2half_rn(v2);
                PHh[2 * ((pA + 4) * 64 + esB) + sub] = __float2half_rn(v3);
            }
        BARG();   // S3

        // ===== warps0-3: GEMM2 (m = hid @ W2) | warps4-7: GEMM3a (e-part) ====
        float acc2[2][4][4];
        #pragma unroll
        for (int mt = 0; mt < 2; mt++)
            #pragma unroll
            for (int nt = 0; nt < 4; nt++)
                #pragma unroll
                for (int q = 0; q < 4; q++) acc2[mt][nt][q] = 0.f;

        if (w < 4) {
            #pragma unroll 2
            for (int kt = 0; kt < 8; kt++) {
                const int k8 = kt * 8;
                uint32_t av[2][4];
                #pragma unroll
                for (int mt = 0; mt < 2; mt++) {
                    int r = c0w2 + 16 * mt + g;
                    av[mt][0] = W2w[r * 68 + k8 + tig];
                    av[mt][1] = W2w[(r + 8) * 68 + k8 + tig];
                    av[mt][2] = W2w[r * 68 + k8 + tig + 4];
                    av[mt][3] = W2w[(r + 8) * 68 + k8 + tig + 4];
                }
                uint32_t bv[4][2];
                const int p0 = 32 + k8 + tig;
                #pragma unroll
                for (int nt = 0; nt < 4; nt++) {
                    int es = (e0w2 + nt * 8 + g) ^ swz;
                    bv[nt][0] = PW[p0 * 64 + es];
                    bv[nt][1] = PW[(p0 + 4) * 64 + es];
                }
                #pragma unroll
                for (int mt = 0; mt < 2; mt++)
                    #pragma unroll
                    for (int nt = 0; nt < 4; nt++)
                        mma16(acc2[mt][nt], av[mt], bv[nt]);
            }
        } else {
            #pragma unroll 2
            for (int kt = 0; kt < 4; kt++) {
                const int k8 = kt * 8;
                uint32_t av[2][4];
                #pragma unroll
                for (int mt = 0; mt < 2; mt++) {
                    int r = c0w2 + 16 * mt + g;
                    av[mt][0] = WEw[r * 68 + k8 + tig];
                    av[mt][1] = WEw[(r + 8) * 68 + k8 + tig];
                    av[mt][2] = WEw[r * 68 + k8 + tig + 4];
                    av[mt][3] = WEw[(r + 8) * 68 + k8 + tig + 4];
                }
                uint32_t bv[4][2];
                const int p0 = k8 + tig;
                #pragma unroll
                for (int nt = 0; nt < 4; nt++) {
                    int es = (e0w2 + nt * 8 + g) ^ swz;
                    bv[nt][0] = PW[p0 * 64 + es];
                    bv[nt][1] = PW[(p0 + 4) * 64 + es];
                }
                #pragma unroll
                for (int mt = 0; mt < 2; mt++)
                    #pragma unroll
                    for (int nt = 0; nt < 4; nt++)
                        mma16(acc2[mt][nt], av[mt], bv[nt]);
            }
        }
        BARG();   // S4

        // ===== epilogue2 (w0-3): m -> planes p 32..63 (fp16) + mf (fp32) =====
        if (w < 4) {
            #pragma unroll
            for (int mt = 0; mt < 2; mt++)
                #pragma unroll
                for (int nt = 0; nt < 4; nt++) {
                    int cA = c0w2 + 16 * mt + g;
                    int eA = e0w2 + 8 * nt + 2 * tig;
                    float v0 = acc2[mt][nt][0] + bi2[cA];
                    float v1 = acc2[mt][nt][1] + bi2[cA];
                    float v2 = acc2[mt][nt][2] + bi2[cA + 8];
                    float v3 = acc2[mt][nt][3] + bi2[cA + 8];
                    int pA = 32 + (cA >> 1);
                    int sub = cA & 1;
                    int sw0 = (pA & 3) << 3;
                    int esA = eA ^ sw0, esB = (eA + 1) ^ sw0;
                    PHh[2 * (pA * 64 + esA) + sub]       = __float2half_rn(v0);
                    PHh[2 * (pA * 64 + esB) + sub]       = __float2half_rn(v1);
                    PHh[2 * ((pA + 4) * 64 + esA) + sub] = __float2half_rn(v2);
                    PHh[2 * ((pA + 4) * 64 + esB) + sub] = __float2half_rn(v3);
                    mf[eA * 65 + cA]           = v0;
                    mf[(eA + 1) * 65 + cA]     = v1;
                    mf[eA * 65 + cA + 8]       = v2;
                    mf[(eA + 1) * 65 + cA + 8] = v3;
                }
        }
        BARG();   // S5

        if (w >= 4) {
            // ===== GEMM3b: += m @ We[64:128]  (m at p 32..63) ================
            #pragma unroll 2
            for (int kt = 4; kt < 8; kt++) {
                const int k8 = kt * 8;
                uint32_t av[2][4];
                #pragma unroll
                for (int mt = 0; mt < 2; mt++) {
                    int r = c0w2 + 16 * mt + g;
                    av[mt][0] = WEw[r * 68 + k8 + tig];
                    av[mt][1] = WEw[(r + 8) * 68 + k8 + tig];
                    av[mt][2] = WEw[r * 68 + k8 + tig + 4];
                    av[mt][3] = WEw[(r + 8) * 68 + k8 + tig + 4];
                }
                uint32_t bv[4][2];
                const int p0 = k8 + tig;
                #pragma unroll
                for (int nt = 0; nt < 4; nt++) {
                    int es = (e0w2 + nt * 8 + g) ^ swz;
                    bv[nt][0] = PW[p0 * 64 + es];
                    bv[nt][1] = PW[(p0 + 4) * 64 + es];
                }
                #pragma unroll
                for (int mt = 0; mt < 2; mt++)
                    #pragma unroll
                    for (int nt = 0; nt < 4; nt++)
                        mma16(acc2[mt][nt], av[mt], bv[nt]);
            }
            // ===== epilogue3: e_new = relu(acc+be) -> gmem ===================
            #pragma unroll
            for (int mt = 0; mt < 2; mt++)
                #pragma unroll
                for (int nt = 0; nt < 4; nt++) {
                    int cA = c0w2 + 16 * mt + g;
                    int eA = e0w2 + 8 * nt + 2 * tig;
                    float* d0 = out_e + (size_t)(base + eA) * D;
                    float* d1 = out_e + (size_t)(base + eA + 1) * D;
                    d0[cA]     = fmaxf(acc2[mt][nt][0] + bie[cA], 0.f);
                    d1[cA]     = fmaxf(acc2[mt][nt][1] + bie[cA], 0.f);
                    d0[cA + 8] = fmaxf(acc2[mt][nt][2] + bie[cA + 8], 0.f);
                    d1[cA + 8] = fmaxf(acc2[mt][nt][3] + bie[cA + 8], 0.f);
                }
        } else {
            // ===== scatter: atomicAdd m (fp32) into g_agg ====================
            const int el = lt & 63;
            const int hf = lt >> 6;
            const int r  = ridx[el];
            const float* mrow = mf + el * 65 + hf * 32;
            float* dstp = g_agg + (size_t)r * D + hf * 32;
            #pragma unroll 8
            for (int c = 0; c < 32; c++) atomicAdd(dstp + c, mrow[c]);
        }
    }
    #undef BARG
}

// ---------------- node kernel: h_new = relu([h | agg] @ W_node + b) ----------
#define NT    32
#define NPAD  36
#define NOFF_W 0
#define NOFF_B (NOFF_W + DH * D)
#define NOFF_X (NOFF_B + D)
#define SMEM_NODE_FLOATS (NOFF_X + DH * NPAD)
#define SMEM_NODE_BYTES  (SMEM_NODE_FLOATS * 4)

__global__ void __launch_bounds__(128)
node_kernel(const float* __restrict__ h,
            const float* __restrict__ Wn, const float* __restrict__ bn,
            float* __restrict__ out_h)
{
    extern __shared__ float sm[];
    const int tid = threadIdx.x;

    for (int i = tid; i < DH * D / 4; i += 128)
        ((float4*)(sm + NOFF_W))[i] = ((const float4*)Wn)[i];
    if (tid < D) sm[NOFF_B + tid] = bn[tid];
    __syncthreads();

    const int nl   = tid >> 2;
    const int part = tid & 3;
    const int ng   = tid >> 4;
    const int cgc  = tid & 15;

    const int n_tiles = N_NODES / NT;
    for (int tile = blockIdx.x; tile < n_tiles; tile += gridDim.x) {
        const int base = tile * NT;
        {
            const float4* hp = (const float4*)(h + (size_t)(base + nl) * D) + part * 4;
            const float4* ap = (const float4*)(g_agg + (size_t)(base + nl) * D) + part * 4;
            #pragma unroll
            for (int q = 0; q < 4; q++) {
                float4 v = hp[q];
                int k0 = part * 16 + q * 4;
                sm[NOFF_X + (k0 + 0) * NPAD + nl] = v.x;
                sm[NOFF_X + (k0 + 1) * NPAD + nl] = v.y;
                sm[NOFF_X + (k0 + 2) * NPAD + nl] = v.z;
                sm[NOFF_X + (k0 + 3) * NPAD + nl] = v.w;
            }
            #pragma unroll
            for (int q = 0; q < 4; q++) {
                float4 v = ap[q];
                int k0 = 64 + part * 16 + q * 4;
                sm[NOFF_X + (k0 + 0) * NPAD + nl] = v.x;
                sm[NOFF_X + (k0 + 1) * NPAD + nl] = v.y;
                sm[NOFF_X + (k0 + 2) * NPAD + nl] = v.z;
                sm[NOFF_X + (k0 + 3) * NPAD + nl] = v.w;
            }
        }
        __syncthreads();

        float acc[4][4];
        #pragma unroll
        for (int i = 0; i < 4; i++)
            #pragma unroll
            for (int j = 0; j < 4; j++) acc[i][j] = 0.f;

        const float* Xb = sm + NOFF_X + ng * 4;
        const float* Wb = sm + NOFF_W + cgc * 4;
        #pragma unroll 4
        for (int k = 0; k < DH; k++) {
            float4 a = *(const float4*)(Xb + k * NPAD);
            float4 wv4 = *(const float4*)(Wb + k * D);
            float av[4] = {a.x, a.y, a.z, a.w};
            float wv[4] = {wv4.x, wv4.y, wv4.z, wv4.w};
            #pragma unroll
            for (int i = 0; i < 4; i++)
                #pragma unroll
                for (int j = 0; j < 4; j++)
                    acc[i][j] = fmaf(av[i], wv[j], acc[i][j]);
        }
        float bb[4];
        #pragma unroll
        for (int j = 0; j < 4; j++) bb[j] = sm[NOFF_B + cgc * 4 + j];
        #pragma unroll
        for (int i = 0; i < 4; i++) {
            float4 v;
            v.x = fmaxf(acc[i][0] + bb[0], 0.f);
            v.y = fmaxf(acc[i][1] + bb[1], 0.f);
            v.z = fmaxf(acc[i][2] + bb[2], 0.f);
            v.w = fmaxf(acc[i][3] + bb[3], 0.f);
            *(float4*)(out_h + (size_t)(base + ng * 4 + i) * D + cgc * 4) = v;
        }
        __syncthreads();
    }
}

// ---------------- launch -----------------------------------------------------
extern "C" void kernel_launch(void* const* d_in, const int* in_sizes, int n_in,
                              void* d_out, int out_size)
{
    const float* h        = (const float*)d_in[0];
    const float* e        = (const float*)d_in[1];
    const int*   senders  = (const int*)d_in[2];
    const int*   receivers= (const int*)d_in[3];
    const float* W1       = (const float*)d_in[4];
    const float* b1       = (const float*)d_in[5];
    const float* W2       = (const float*)d_in[6];
    const float* b2       = (const float*)d_in[7];
    const float* Wn       = (const float*)d_in[8];
    const float* bn       = (const float*)d_in[9];
    const float* We       = (const float*)d_in[10];
    const float* be       = (const float*)d_in[11];

    float* out_h = (float*)d_out;
    float* out_e = out_h + (size_t)N_NODES * D;

    cudaFuncSetAttribute(edge_kernel, cudaFuncAttributeMaxDynamicSharedMemorySize,
                         SMEM_EDGE_BYTES);
    cudaFuncSetAttribute(node_kernel, cudaFuncAttributeMaxDynamicSharedMemorySize,
                         SMEM_NODE_BYTES);

    zero_agg_kernel<<<(N_NODES * D / 4 + 255) / 256, 256>>>();
    edge_kernel<<<EK_GRID, EK_THREADS, SMEM_EDGE_BYTES>>>(
        h, e, senders, receivers, W1, b1, W2, b2, We, be, out_e);
    node_kernel<<<1480, 128, SMEM_NODE_BYTES>>>(h, Wn, bn, out_h);
}